// round 9
// baseline (speedup 1.0000x reference)
#include <cuda_runtime.h>
#include <cuda_bf16.h>
#include <cfloat>

#define NA 8400
#define NB 32
#define NT 50
#define NK 10
#define NC 80
#define NCAND 108          // 3 levels * 6x6 window
#define ASSIGN_BLOCKS 200  // 8 warps (targets) per block
#define BCE_BLOCKS 132     // 2 float4 per thread: 132*256*2 = 67584 >= 67200
#define BCE_V4 67200       // NB*NA/4 float4 obj elements
#define MAXPOS (NB * NT * NK)

// ---- persistent scratch (device globals; zero at load, every launch restores zero) ----
__device__ int      g_flag[NB * NA];   // dedup flags; reset by last block via g_list
__device__ int      g_list[MAXPOS];    // flagged indices (read only [0, g_cnt) same launch)
__device__ unsigned g_cnt;             // list cursor; reset by last block
__device__ unsigned g_done;            // block-done counter; reset by last block
__device__ double   g_acc[4];          // 0:num_pos 1:reg_sum 2:cls_sum 3:obj_sum; reset by last block

__device__ __forceinline__ void anchor_decode(int a, int& lvl, int& gx, int& gy,
                                              int& W, int& hw, float& s) {
    if (a < 6400)      { lvl = 0; W = 80; hw = 6400; gx = a % 80;            gy = a / 80;            s = 8.f;  }
    else if (a < 8000) { lvl = 1; W = 40; hw = 1600; int al = a - 6400; gx = al % 40; gy = al / 40; s = 16.f; }
    else               { lvl = 2; W = 20; hw = 400;  int al = a - 8000; gx = al % 20; gy = al / 20; s = 32.f; }
}

// BCEWithLogits fast-math variants (feed only the summed losses, not selection)
__device__ __forceinline__ float bce0(float x) {
    return fmaxf(x, 0.f) + __logf(1.f + __expf(-fabsf(x)));
}
__device__ __forceinline__ float bce(float x, float t) {
    return fmaxf(x, 0.f) - x * t + __logf(1.f + __expf(-fabsf(x)));
}

// leftmost of the 6 nearest in-range columns/rows
__device__ __forceinline__ int win_base(float tc, float s, int W) {
    float u = tc / s - 0.5f;
    int f = (int)floorf(u) - 2;
    if (f < 0) f = 0;
    if (f > W - 6) f = W - 6;
    return f;
}

// ---- single fused kernel ----
__global__ void __launch_bounds__(256) k_main(
    const float* __restrict__ p3_cls, const float* __restrict__ p3_reg, const float* __restrict__ p3_obj,
    const float* __restrict__ p4_cls, const float* __restrict__ p4_reg, const float* __restrict__ p4_obj,
    const float* __restrict__ p5_cls, const float* __restrict__ p5_reg, const float* __restrict__ p5_obj,
    const float* __restrict__ targets, float* __restrict__ out)
{
    const unsigned FULL = 0xffffffffu;
    int lane = threadIdx.x & 31;
    int wid_in_blk = threadIdx.x >> 5;

    if (blockIdx.x >= ASSIGN_BLOCKS) {
        // ======== background objectness BCE: bce(x,0) over all B*A anchors ========
        int t0 = ((blockIdx.x - ASSIGN_BLOCKS) * 256 + threadIdx.x) * 2;
        float acc = 0.f;
#pragma unroll
        for (int q = 0; q < 2; q++) {
            int v = t0 + q;
            if (v < BCE_V4) {
                const float4* p; int off;
                if (v < 51200)      { p = (const float4*)p3_obj; off = v; }
                else if (v < 64000) { p = (const float4*)p4_obj; off = v - 51200; }
                else                { p = (const float4*)p5_obj; off = v - 64000; }
                float4 x4 = p[off];
                acc += bce0(x4.x) + bce0(x4.y) + bce0(x4.z) + bce0(x4.w);
            }
        }
#pragma unroll
        for (int off = 16; off; off >>= 1) acc += __shfl_xor_sync(FULL, acc, off);
        __shared__ float sm[8];
        if (lane == 0) sm[wid_in_blk] = acc;
        __syncthreads();
        if (wid_in_blk == 0) {
            acc = (lane < 8) ? sm[lane] : 0.f;
#pragma unroll
            for (int off = 4; off; off >>= 1) acc += __shfl_xor_sync(FULL, acc, off);
            if (lane == 0) atomicAdd(&g_acc[3], (double)acc);
        }
    } else {
        // ======== assignment path: one warp per (b,t) ========
        int wg = blockIdx.x * 8 + wid_in_blk;
        int b = wg / NT;
        const float* tgt = targets + wg * 5;
        float tw = tgt[2], th = tgt[3];
        float tcx = tgt[0] + 0.5f * tw;
        float tcy = tgt[1] + 0.5f * th;
        int tcls = (int)tgt[4];

        int x0a = win_base(tcx,  8.f, 80), y0a = win_base(tcy,  8.f, 80);
        int x0b = win_base(tcx, 16.f, 40), y0b = win_base(tcy, 16.f, 40);
        int x0c = win_base(tcx, 32.f, 20), y0c = win_base(tcy, 32.f, 20);

        // per-lane sorted-4 candidates (asc by (dist, idx)); 6x6 window per level
        // provably contains each level's top-10, hence the global top-10.
        float cd[4]; int ci[4];
#pragma unroll
        for (int j = 0; j < 4; j++) { cd[j] = FLT_MAX; ci[j] = 0x7FFFFFFF; }

#pragma unroll
        for (int t = 0; t < 4; t++) {
            int c = lane + (t << 5);
            if (c >= NCAND) break;
            int lvl = (c >= 72) ? 2 : (c >= 36) ? 1 : 0;
            int w6 = c - 36 * lvl;
            int dxi = w6 % 6, dyi = w6 / 6;
            int gx, gy, W, basei; float s;
            if (lvl == 0)      { gx = x0a + dxi; gy = y0a + dyi; W = 80; basei = 0;    s = 8.f;  }
            else if (lvl == 1) { gx = x0b + dxi; gy = y0b + dyi; W = 40; basei = 6400; s = 16.f; }
            else               { gx = x0c + dxi; gy = y0c + dyi; W = 20; basei = 8000; s = 32.f; }
            int idx = basei + gy * W + gx;
            float acx = (float)gx * s + 0.5f * s;
            float acy = (float)gy * s + 0.5f * s;
            float dx = __fsub_rn(acx, tcx);
            float dy = __fsub_rn(acy, tcy);
            float dist = __fsqrt_rn(__fadd_rn(__fmul_rn(dx, dx), __fmul_rn(dy, dy)));
            float vcd = dist; int vci = idx;
#pragma unroll
            for (int j = 0; j < 4; j++) {
                bool sw = (vcd < cd[j]) || (vcd == cd[j] && vci < ci[j]);
                if (sw) { float td = cd[j]; int ti = ci[j]; cd[j] = vcd; ci[j] = vci; vcd = td; vci = ti; }
            }
        }

        // warp merge: 10 rounds of stable lexicographic min (dist asc, idx asc)
        int res_a = 0;
#pragma unroll 1
        for (int k = 0; k < NK; k++) {
            float bd = cd[0]; int bi = ci[0];
#pragma unroll
            for (int off = 16; off; off >>= 1) {
                float od = __shfl_xor_sync(FULL, bd, off);
                int   oi = __shfl_xor_sync(FULL, bi, off);
                if (od < bd || (od == bd && oi < bi)) { bd = od; bi = oi; }
            }
            if (ci[0] == bi) {
#pragma unroll
                for (int j = 0; j < 3; j++) { cd[j] = cd[j + 1]; ci[j] = ci[j + 1]; }
                cd[3] = FLT_MAX; ci[3] = 0x7FFFFFFF;
            }
            if (lane == k) res_a = bi;
        }

        // lane k (<10): decode pred box, IoU + CIoU (selection-critical: precise math)
        bool have = (lane < NK);
        float iou = -FLT_MAX, ciou = 0.f;
        int my_a = res_a;
        int lvl = 0, gx = 0, gy = 0, W = 0, hw = 0; float s = 0.f;
        if (have) {
            anchor_decode(my_a, lvl, gx, gy, W, hw, s);
            const float* regp = (lvl == 0) ? p3_reg : (lvl == 1) ? p4_reg : p5_reg;
            int base = (b * 4) * hw + gy * W + gx;
            float r0 = regp[base];
            float r1 = regp[base + hw];
            float r2 = regp[base + 2 * hw];
            float r3 = regp[base + 3 * hw];
            float pcx = ((float)gx + 1.f / (1.f + expf(-r0))) * s;
            float pcy = ((float)gy + 1.f / (1.f + expf(-r1))) * s;
            float pw  = expf(r2) * s;
            float ph  = expf(r3) * s;
            float x11 = pcx - pw * 0.5f, x12 = pcx + pw * 0.5f;
            float y11 = pcy - ph * 0.5f, y12 = pcy + ph * 0.5f;
            float x21 = tcx - tw * 0.5f, x22 = tcx + tw * 0.5f;
            float y21 = tcy - th * 0.5f, y22 = tcy + th * 0.5f;
            float iw = fmaxf(fminf(x12, x22) - fmaxf(x11, x21), 0.f);
            float ih = fmaxf(fminf(y12, y22) - fmaxf(y11, y21), 0.f);
            float inter = iw * ih;
            float a1 = (x12 - x11) * (y12 - y11);
            float a2 = (x22 - x21) * (y22 - y21);
            float uni = a1 + a2 - inter + 1e-7f;
            iou = inter / uni;
            float cw = fmaxf(x12, x22) - fminf(x11, x21);
            float chh = fmaxf(y12, y22) - fminf(y11, y21);
            float c2 = cw * cw + chh * chh + 1e-7f;
            float ddx = x21 + x22 - x11 - x12;
            float ddy = y21 + y22 - y11 - y12;
            float rho2 = (ddx * ddx + ddy * ddy) * 0.25f;
            float dv = atanf((x22 - x21) / ((y22 - y21) + 1e-7f))
                     - atanf((x12 - x11) / ((y12 - y11) + 1e-7f));
            float v = (float)(4.0 / (3.14159 * 3.14159)) * dv * dv;
            float alpha = v / ((1.f - iou) + v + 1e-7f);
            ciou = iou - (rho2 / c2 + v * alpha);
        }

        // argmax(iou) over K, first-max tie-break
        float am = iou; int amk = lane;
#pragma unroll
        for (int off = 16; off; off >>= 1) {
            float om = __shfl_xor_sync(FULL, am, off);
            int   ok = __shfl_xor_sync(FULL, amk, off);
            if (om > am || (om == am && ok < amk)) { am = om; amk = ok; }
        }

        unsigned vb = __ballot_sync(FULL, have && (iou > 0.1f));
        bool w = have && (vb ? (iou > 0.1f) : (lane == amk));
        unsigned wb = __ballot_sync(FULL, w);
        int npos = __popc(wb);

        float regc = w ? (1.f - ciou) : 0.f;
#pragma unroll
        for (int off = 16; off; off >>= 1) regc += __shfl_xor_sync(FULL, regc, off);

        // obj correction: bce(x,1)-bce(x,0) == -x at each UNIQUE assigned (b,anchor)
        float corr = 0.f;
        if (w) {
            int i = b * NA + my_a;
            if (atomicExch(&g_flag[i], 1) == 0) {
                unsigned pos = atomicAdd(&g_cnt, 1u);
                g_list[pos] = i;
                const float* objp = (lvl == 0) ? p3_obj : (lvl == 1) ? p4_obj : p5_obj;
                corr = -objp[b * hw + gy * W + gx];
            }
        }
#pragma unroll
        for (int off = 16; off; off >>= 1) corr += __shfl_xor_sync(FULL, corr, off);

        // cls loss: flatten (assigned anchor, class) pairs across lanes — all loads
        // independent (one MLP batch instead of up to 10 serial latency rounds)
        float clsacc = 0.f;
        int total = npos * NC;
        int iters = (total + 31) >> 5;
        for (int it = 0; it < iters; it++) {
            int p = lane + (it << 5);
            bool act = p < total;
            int j = act ? (p / NC) : 0;            // which assigned anchor
            int c = p - j * NC;                    // class
            int kj = __fns(wb, 0, j + 1);          // lane holding j-th winner
            int ak = __shfl_sync(FULL, my_a, kj);  // uniform trip count: all lanes shfl
            if (act) {
                int l2, gx2, gy2, W2, hw2; float s2;
                anchor_decode(ak, l2, gx2, gy2, W2, hw2, s2);
                const float* clsp = (l2 == 0) ? p3_cls : (l2 == 1) ? p4_cls : p5_cls;
                float x = clsp[(b * NC + c) * hw2 + gy2 * W2 + gx2];
                clsacc += bce(x, (c == tcls) ? 1.f : 0.f);
            }
        }
#pragma unroll
        for (int off = 16; off; off >>= 1) clsacc += __shfl_xor_sync(FULL, clsacc, off);

        // block reduction -> 4 double atomics per block
        __shared__ float s_np[8], s_reg[8], s_cls[8], s_obj[8];
        if (lane == 0) {
            s_np[wid_in_blk]  = (float)npos;
            s_reg[wid_in_blk] = regc;
            s_cls[wid_in_blk] = clsacc;
            s_obj[wid_in_blk] = corr;
        }
        __syncthreads();
        if (wid_in_blk == 0 && lane < 8) {
            float vnp = s_np[lane], vrg = s_reg[lane], vcl = s_cls[lane], vob = s_obj[lane];
#pragma unroll
            for (int off = 4; off; off >>= 1) {
                vnp += __shfl_xor_sync(0xffu, vnp, off);
                vrg += __shfl_xor_sync(0xffu, vrg, off);
                vcl += __shfl_xor_sync(0xffu, vcl, off);
                vob += __shfl_xor_sync(0xffu, vob, off);
            }
            if (lane == 0) {
                atomicAdd(&g_acc[0], (double)vnp);
                atomicAdd(&g_acc[1], (double)vrg);
                atomicAdd(&g_acc[2], (double)vcl);
                atomicAdd(&g_acc[3], (double)vob);
            }
        }
    }

    // ======== common tail: last block finalizes + resets scratch ========
    __shared__ int s_last;
    __syncthreads();                       // all per-block atomics issued before signal
    if (threadIdx.x == 0) {
        __threadfence();
        unsigned t = atomicAdd(&g_done, 1u);
        s_last = (t == gridDim.x - 1) ? 1 : 0;
    }
    __syncthreads();
    if (s_last) {
        __threadfence();                   // acquire: see all other blocks' writes
        unsigned cnt = g_cnt;
        for (unsigned i = threadIdx.x; i < cnt; i += 256)
            g_flag[g_list[i]] = 0;         // reset only touched flags
        if (threadIdx.x == 0) {
            double np = atomicAdd(&g_acc[0], 0.0);
            double rg = atomicAdd(&g_acc[1], 0.0);
            double cl = atomicAdd(&g_acc[2], 0.0);
            double ob = atomicAdd(&g_acc[3], 0.0);
            if (np < 1.0) np = 1.0;
            double reg_l = rg / np, cls_l = cl / np, obj_l = ob / np;
            out[0] = (float)(5.0 * reg_l + obj_l + cls_l);
            out[1] = (float)reg_l;
            out[2] = (float)obj_l;
            out[3] = (float)cls_l;
            g_acc[0] = 0.0; g_acc[1] = 0.0; g_acc[2] = 0.0; g_acc[3] = 0.0;
            g_cnt = 0u; g_done = 0u;
        }
    }
}

extern "C" void kernel_launch(void* const* d_in, const int* in_sizes, int n_in,
                              void* d_out, int out_size) {
    const float* p3_cls  = (const float*)d_in[0];
    const float* p3_reg  = (const float*)d_in[1];
    const float* p3_obj  = (const float*)d_in[2];
    const float* p4_cls  = (const float*)d_in[3];
    const float* p4_reg  = (const float*)d_in[4];
    const float* p4_obj  = (const float*)d_in[5];
    const float* p5_cls  = (const float*)d_in[6];
    const float* p5_reg  = (const float*)d_in[7];
    const float* p5_obj  = (const float*)d_in[8];
    const float* targets = (const float*)d_in[9];

    k_main<<<ASSIGN_BLOCKS + BCE_BLOCKS, 256>>>(p3_cls, p3_reg, p3_obj,
                                                p4_cls, p4_reg, p4_obj,
                                                p5_cls, p5_reg, p5_obj,
                                                targets, (float*)d_out);
}

// round 10
// speedup vs baseline: 1.2912x; 1.2912x over previous
#include <cuda_runtime.h>
#include <cuda_bf16.h>
#include <cfloat>

#define NA 8400
#define NB 32
#define NT 50
#define NK 10
#define NC 80
#define NCAND 108          // 3 levels * 6x6 window
#define ASSIGN_BLOCKS 200  // 8 warps (targets) per block
#define BCE_BLOCKS 132     // 2 float4 per thread: 132*256*2 = 67584 >= 67200
#define BCE_V4 67200       // NB*NA/4 float4 obj elements
#define MAXPOS (NB * NT * NK)

// ---- persistent scratch (device globals; zero at load, every launch restores zero) ----
__device__ int      g_flag[NB * NA];   // dedup flags; reset by last block via g_list
__device__ int      g_list[MAXPOS];    // flagged indices (read only [0, g_cnt) same launch)
__device__ unsigned g_cnt;             // list cursor; reset by last block
__device__ unsigned g_done;            // block-done counter; reset by last block
__device__ double   g_acc[4];          // 0:num_pos 1:reg_sum 2:cls_sum 3:obj_sum; reset by last block

__device__ __forceinline__ void anchor_decode(int a, int& lvl, int& gx, int& gy,
                                              int& W, int& hw, float& s) {
    if (a < 6400)      { lvl = 0; W = 80; hw = 6400; gx = a % 80;            gy = a / 80;            s = 8.f;  }
    else if (a < 8000) { lvl = 1; W = 40; hw = 1600; int al = a - 6400; gx = al % 40; gy = al / 40; s = 16.f; }
    else               { lvl = 2; W = 20; hw = 400;  int al = a - 8000; gx = al % 20; gy = al / 20; s = 32.f; }
}

// BCEWithLogits fast-math variants (feed only the summed losses, not selection)
__device__ __forceinline__ float bce0(float x) {
    return fmaxf(x, 0.f) + __logf(1.f + __expf(-fabsf(x)));
}

// leftmost of the 6 nearest in-range columns/rows
__device__ __forceinline__ int win_base(float tc, float s, int W) {
    float u = tc / s - 0.5f;
    int f = (int)floorf(u) - 2;
    if (f < 0) f = 0;
    if (f > W - 6) f = W - 6;
    return f;
}

// ---- single fused kernel ----
__global__ void __launch_bounds__(256) k_main(
    const float* __restrict__ p3_cls, const float* __restrict__ p3_reg, const float* __restrict__ p3_obj,
    const float* __restrict__ p4_cls, const float* __restrict__ p4_reg, const float* __restrict__ p4_obj,
    const float* __restrict__ p5_cls, const float* __restrict__ p5_reg, const float* __restrict__ p5_obj,
    const float* __restrict__ targets, float* __restrict__ out)
{
    const unsigned FULL = 0xffffffffu;
    int lane = threadIdx.x & 31;
    int wid_in_blk = threadIdx.x >> 5;

    // per-warp anchor tables for the cls gather (indexable -> shared, not regs)
    __shared__ const float* s_ptr[8][NK];   // cls base ptr at (b, :, gy, gx)
    __shared__ int          s_hw[8][NK];    // class stride for that level

    if (blockIdx.x >= ASSIGN_BLOCKS) {
        // ======== background objectness BCE: bce(x,0) over all B*A anchors ========
        int t0 = ((blockIdx.x - ASSIGN_BLOCKS) * 256 + threadIdx.x) * 2;
        float acc = 0.f;
#pragma unroll
        for (int q = 0; q < 2; q++) {
            int v = t0 + q;
            if (v < BCE_V4) {
                const float4* p; int off;
                if (v < 51200)      { p = (const float4*)p3_obj; off = v; }
                else if (v < 64000) { p = (const float4*)p4_obj; off = v - 51200; }
                else                { p = (const float4*)p5_obj; off = v - 64000; }
                float4 x4 = p[off];
                acc += bce0(x4.x) + bce0(x4.y) + bce0(x4.z) + bce0(x4.w);
            }
        }
#pragma unroll
        for (int off = 16; off; off >>= 1) acc += __shfl_xor_sync(FULL, acc, off);
        __shared__ float sm[8];
        if (lane == 0) sm[wid_in_blk] = acc;
        __syncthreads();
        if (wid_in_blk == 0) {
            acc = (lane < 8) ? sm[lane] : 0.f;
#pragma unroll
            for (int off = 4; off; off >>= 1) acc += __shfl_xor_sync(FULL, acc, off);
            if (lane == 0) atomicAdd(&g_acc[3], (double)acc);
        }
    } else {
        // ======== assignment path: one warp per (b,t) ========
        int wg = blockIdx.x * 8 + wid_in_blk;
        int b = wg / NT;
        const float* tgt = targets + wg * 5;
        float tw = tgt[2], th = tgt[3];
        float tcx = tgt[0] + 0.5f * tw;
        float tcy = tgt[1] + 0.5f * th;
        int tcls = (int)tgt[4];

        int x0a = win_base(tcx,  8.f, 80), y0a = win_base(tcy,  8.f, 80);
        int x0b = win_base(tcx, 16.f, 40), y0b = win_base(tcy, 16.f, 40);
        int x0c = win_base(tcx, 32.f, 20), y0c = win_base(tcy, 32.f, 20);

        // per-lane sorted-4 candidates (asc by (dist, idx)); 6x6 window per level
        // provably contains each level's top-10, hence the global top-10.
        float cd[4]; int ci[4];
#pragma unroll
        for (int j = 0; j < 4; j++) { cd[j] = FLT_MAX; ci[j] = 0x7FFFFFFF; }

#pragma unroll
        for (int t = 0; t < 4; t++) {
            int c = lane + (t << 5);
            if (c >= NCAND) break;
            int lvl = (c >= 72) ? 2 : (c >= 36) ? 1 : 0;
            int w6 = c - 36 * lvl;
            int dxi = w6 % 6, dyi = w6 / 6;
            int gx, gy, W, basei; float s;
            if (lvl == 0)      { gx = x0a + dxi; gy = y0a + dyi; W = 80; basei = 0;    s = 8.f;  }
            else if (lvl == 1) { gx = x0b + dxi; gy = y0b + dyi; W = 40; basei = 6400; s = 16.f; }
            else               { gx = x0c + dxi; gy = y0c + dyi; W = 20; basei = 8000; s = 32.f; }
            int idx = basei + gy * W + gx;
            float acx = (float)gx * s + 0.5f * s;
            float acy = (float)gy * s + 0.5f * s;
            float dx = __fsub_rn(acx, tcx);
            float dy = __fsub_rn(acy, tcy);
            float dist = __fsqrt_rn(__fadd_rn(__fmul_rn(dx, dx), __fmul_rn(dy, dy)));
            float vcd = dist; int vci = idx;
#pragma unroll
            for (int j = 0; j < 4; j++) {
                bool sw = (vcd < cd[j]) || (vcd == cd[j] && vci < ci[j]);
                if (sw) { float td = cd[j]; int ti = ci[j]; cd[j] = vcd; ci[j] = vci; vcd = td; vci = ti; }
            }
        }

        // warp merge: 10 rounds of stable lexicographic min (dist asc, idx asc)
        int res_a = 0;
#pragma unroll 1
        for (int k = 0; k < NK; k++) {
            float bd = cd[0]; int bi = ci[0];
#pragma unroll
            for (int off = 16; off; off >>= 1) {
                float od = __shfl_xor_sync(FULL, bd, off);
                int   oi = __shfl_xor_sync(FULL, bi, off);
                if (od < bd || (od == bd && oi < bi)) { bd = od; bi = oi; }
            }
            if (ci[0] == bi) {
#pragma unroll
                for (int j = 0; j < 3; j++) { cd[j] = cd[j + 1]; ci[j] = ci[j + 1]; }
                cd[3] = FLT_MAX; ci[3] = 0x7FFFFFFF;
            }
            if (lane == k) res_a = bi;
        }

        // lane k (<10): decode pred box, IoU + CIoU (selection-critical: precise math)
        bool have = (lane < NK);
        float iou = -FLT_MAX, ciou = 0.f;
        int my_a = res_a;
        int lvl = 0, gx = 0, gy = 0, W = 0, hw = 0; float s = 0.f;
        if (have) {
            anchor_decode(my_a, lvl, gx, gy, W, hw, s);
            const float* regp = (lvl == 0) ? p3_reg : (lvl == 1) ? p4_reg : p5_reg;
            int base = (b * 4) * hw + gy * W + gx;
            float r0 = regp[base];
            float r1 = regp[base + hw];
            float r2 = regp[base + 2 * hw];
            float r3 = regp[base + 3 * hw];
            float pcx = ((float)gx + 1.f / (1.f + expf(-r0))) * s;
            float pcy = ((float)gy + 1.f / (1.f + expf(-r1))) * s;
            float pw  = expf(r2) * s;
            float ph  = expf(r3) * s;
            float x11 = pcx - pw * 0.5f, x12 = pcx + pw * 0.5f;
            float y11 = pcy - ph * 0.5f, y12 = pcy + ph * 0.5f;
            float x21 = tcx - tw * 0.5f, x22 = tcx + tw * 0.5f;
            float y21 = tcy - th * 0.5f, y22 = tcy + th * 0.5f;
            float iw = fmaxf(fminf(x12, x22) - fmaxf(x11, x21), 0.f);
            float ih = fmaxf(fminf(y12, y22) - fmaxf(y11, y21), 0.f);
            float inter = iw * ih;
            float a1 = (x12 - x11) * (y12 - y11);
            float a2 = (x22 - x21) * (y22 - y21);
            float uni = a1 + a2 - inter + 1e-7f;
            iou = inter / uni;
            float cw = fmaxf(x12, x22) - fminf(x11, x21);
            float chh = fmaxf(y12, y22) - fminf(y11, y21);
            float c2 = cw * cw + chh * chh + 1e-7f;
            float ddx = x21 + x22 - x11 - x12;
            float ddy = y21 + y22 - y11 - y12;
            float rho2 = (ddx * ddx + ddy * ddy) * 0.25f;
            float dv = atanf((x22 - x21) / ((y22 - y21) + 1e-7f))
                     - atanf((x12 - x11) / ((y12 - y11) + 1e-7f));
            float v = (float)(4.0 / (3.14159 * 3.14159)) * dv * dv;
            float alpha = v / ((1.f - iou) + v + 1e-7f);
            ciou = iou - (rho2 / c2 + v * alpha);
        }

        // argmax(iou) over K, first-max tie-break
        float am = iou; int amk = lane;
#pragma unroll
        for (int off = 16; off; off >>= 1) {
            float om = __shfl_xor_sync(FULL, am, off);
            int   ok = __shfl_xor_sync(FULL, amk, off);
            if (om > am || (om == am && ok < amk)) { am = om; amk = ok; }
        }

        unsigned vb = __ballot_sync(FULL, have && (iou > 0.1f));
        bool w = have && (vb ? (iou > 0.1f) : (lane == amk));
        unsigned wb = __ballot_sync(FULL, w);
        int npos = __popc(wb);

        float regc = w ? (1.f - ciou) : 0.f;
#pragma unroll
        for (int off = 16; off; off >>= 1) regc += __shfl_xor_sync(FULL, regc, off);

        // obj correction: bce(x,1)-bce(x,0) == -x at each UNIQUE assigned (b,anchor);
        // winners also publish their cls gather base into the per-warp table.
        float corr = 0.f;
        if (w) {
            int r = __popc(wb & ((1u << lane) - 1));   // compact rank among winners
            const float* clsp = (lvl == 0) ? p3_cls : (lvl == 1) ? p4_cls : p5_cls;
            s_ptr[wid_in_blk][r] = clsp + (size_t)(b * NC) * hw + gy * W + gx;
            s_hw[wid_in_blk][r]  = hw;
            int i = b * NA + my_a;
            if (atomicExch(&g_flag[i], 1) == 0) {
                unsigned pos = atomicAdd(&g_cnt, 1u);
                g_list[pos] = i;
                const float* objp = (lvl == 0) ? p3_obj : (lvl == 1) ? p4_obj : p5_obj;
                corr = -objp[b * hw + gy * W + gx];
            }
        }
#pragma unroll
        for (int off = 16; off; off >>= 1) corr += __shfl_xor_sync(FULL, corr, off);
        __syncwarp();

        // cls loss: flatten (winner, class) pairs; FULLY UNROLLED 25 iterations
        // (25*32 = 800 = NK*NC max) -> all loads independent, one MLP batch.
        // bce(x, onehot) = bce0(x) - (c==tcls)*x
        float clsacc = 0.f;
        int total = npos * NC;
#pragma unroll
        for (int it = 0; it < 25; it++) {
            int p = lane + (it << 5);
            if (p < total) {
                int j = (unsigned)p / NC;              // div-by-80 -> mul/shift
                int c = p - j * NC;
                const float* ptr = s_ptr[wid_in_blk][j];
                int hwj = s_hw[wid_in_blk][j];
                float x = ptr[c * hwj];
                clsacc += bce0(x) - ((c == tcls) ? x : 0.f);
            }
        }
#pragma unroll
        for (int off = 16; off; off >>= 1) clsacc += __shfl_xor_sync(FULL, clsacc, off);

        // block reduction -> 4 double atomics per block
        __shared__ float s_np[8], s_reg[8], s_cls[8], s_obj[8];
        if (lane == 0) {
            s_np[wid_in_blk]  = (float)npos;
            s_reg[wid_in_blk] = regc;
            s_cls[wid_in_blk] = clsacc;
            s_obj[wid_in_blk] = corr;
        }
        __syncthreads();
        if (wid_in_blk == 0 && lane < 8) {
            float vnp = s_np[lane], vrg = s_reg[lane], vcl = s_cls[lane], vob = s_obj[lane];
#pragma unroll
            for (int off = 4; off; off >>= 1) {
                vnp += __shfl_xor_sync(0xffu, vnp, off);
                vrg += __shfl_xor_sync(0xffu, vrg, off);
                vcl += __shfl_xor_sync(0xffu, vcl, off);
                vob += __shfl_xor_sync(0xffu, vob, off);
            }
            if (lane == 0) {
                atomicAdd(&g_acc[0], (double)vnp);
                atomicAdd(&g_acc[1], (double)vrg);
                atomicAdd(&g_acc[2], (double)vcl);
                atomicAdd(&g_acc[3], (double)vob);
            }
        }
    }

    // ======== common tail: last block finalizes + resets scratch ========
    __shared__ int s_last;
    __syncthreads();                       // all per-block atomics issued before signal
    if (threadIdx.x == 0) {
        __threadfence();
        unsigned t = atomicAdd(&g_done, 1u);
        s_last = (t == gridDim.x - 1) ? 1 : 0;
    }
    __syncthreads();
    if (s_last) {
        __threadfence();                   // acquire: see all other blocks' writes
        unsigned cnt = g_cnt;
        for (unsigned i = threadIdx.x; i < cnt; i += 256)
            g_flag[g_list[i]] = 0;         // reset only touched flags
        if (threadIdx.x == 0) {
            double np = atomicAdd(&g_acc[0], 0.0);
            double rg = atomicAdd(&g_acc[1], 0.0);
            double cl = atomicAdd(&g_acc[2], 0.0);
            double ob = atomicAdd(&g_acc[3], 0.0);
            if (np < 1.0) np = 1.0;
            double reg_l = rg / np, cls_l = cl / np, obj_l = ob / np;
            out[0] = (float)(5.0 * reg_l + obj_l + cls_l);
            out[1] = (float)reg_l;
            out[2] = (float)obj_l;
            out[3] = (float)cls_l;
            g_acc[0] = 0.0; g_acc[1] = 0.0; g_acc[2] = 0.0; g_acc[3] = 0.0;
            g_cnt = 0u; g_done = 0u;
        }
    }
}

extern "C" void kernel_launch(void* const* d_in, const int* in_sizes, int n_in,
                              void* d_out, int out_size) {
    const float* p3_cls  = (const float*)d_in[0];
    const float* p3_reg  = (const float*)d_in[1];
    const float* p3_obj  = (const float*)d_in[2];
    const float* p4_cls  = (const float*)d_in[3];
    const float* p4_reg  = (const float*)d_in[4];
    const float* p4_obj  = (const float*)d_in[5];
    const float* p5_cls  = (const float*)d_in[6];
    const float* p5_reg  = (const float*)d_in[7];
    const float* p5_obj  = (const float*)d_in[8];
    const float* targets = (const float*)d_in[9];

    k_main<<<ASSIGN_BLOCKS + BCE_BLOCKS, 256>>>(p3_cls, p3_reg, p3_obj,
                                                p4_cls, p4_reg, p4_obj,
                                                p5_cls, p5_reg, p5_obj,
                                                targets, (float*)d_out);
}